// round 4
// baseline (speedup 1.0000x reference)
#include <cuda_runtime.h>
#include <math.h>

#define BB   64
#define TT   512
#define NIN  256
#define NH   2048
#define NOUT 256
#define NCTA 128   // 8 n-tiles x 16 k-splits, all co-resident on 148 SMs

// Scratch (device globals; no allocation anywhere)
__device__ float g_X[(size_t)BB * TT * NH];        // [b*T+t][NH]  input projections + b_h
__device__ float g_H[(size_t)(TT + 1) * BB * NH];  // [t][b][NH]   hidden states
__device__ float g_P[(size_t)16 * BB * NH];        // [ks][b][NH]  K-split partials
__device__ unsigned g_bar_arrive = 0;
__device__ unsigned g_bar_release = 0;             // monotonic generation counter

// ---------------------------------------------------------------------------
// GEMM1: g_X = u @ W_uh + b_h     (M=32768, K=256, N=2048), 128x128 tile
// ---------------------------------------------------------------------------
__global__ __launch_bounds__(256) void gemm1_kernel(const float* __restrict__ u,
                                                    const float* __restrict__ W,
                                                    const float* __restrict__ bias) {
    __shared__ float sA[16][129];
    __shared__ float sB[16][128];
    const int m0 = blockIdx.x * 128;
    const int n0 = blockIdx.y * 128;
    const int tid = threadIdx.x;
    const int tcol = tid & 15;
    const int trow = tid >> 4;
    float acc[8][8];
#pragma unroll
    for (int i = 0; i < 8; i++)
#pragma unroll
        for (int j = 0; j < 8; j++) acc[i][j] = 0.f;

    for (int k0 = 0; k0 < NIN; k0 += 16) {
#pragma unroll
        for (int i = 0; i < 8; i++) {
            int idx = tid + i * 256;
            int m = idx >> 4, k = idx & 15;
            sA[k][m] = u[(size_t)(m0 + m) * NIN + k0 + k];
        }
#pragma unroll
        for (int i = 0; i < 8; i++) {
            int idx = tid + i * 256;
            int k = idx >> 7, n = idx & 127;
            sB[k][n] = W[(size_t)(k0 + k) * NH + n0 + n];
        }
        __syncthreads();
#pragma unroll
        for (int kk = 0; kk < 16; kk++) {
            float av[8], bv[8];
#pragma unroll
            for (int i = 0; i < 8; i++) av[i] = sA[kk][trow * 8 + i];
#pragma unroll
            for (int j = 0; j < 8; j++) bv[j] = sB[kk][tcol * 8 + j];
#pragma unroll
            for (int i = 0; i < 8; i++)
#pragma unroll
                for (int j = 0; j < 8; j++) acc[i][j] += av[i] * bv[j];
        }
        __syncthreads();
    }
#pragma unroll
    for (int i = 0; i < 8; i++) {
        int m = m0 + trow * 8 + i;
#pragma unroll
        for (int j = 0; j < 8; j++) {
            int n = n0 + tcol * 8 + j;
            g_X[(size_t)m * NH + n] = acc[i][j] + bias[n];
        }
    }
}

// ---------------------------------------------------------------------------
// Grid barrier (sense via monotonic release counter). All CTAs co-resident.
// ---------------------------------------------------------------------------
__device__ __forceinline__ void grid_bar(unsigned& gen) {
    __threadfence();
    __syncthreads();
    if (threadIdx.x == 0) {
        unsigned prev = atomicAdd(&g_bar_arrive, 1);
        if (prev == NCTA - 1) {
            g_bar_arrive = 0;
            __threadfence();
            atomicAdd(&g_bar_release, 1);
        } else {
            while (*((volatile unsigned*)&g_bar_release) == gen) { }
        }
        gen++;
    }
    __syncthreads();
}

// ---------------------------------------------------------------------------
// Persistent recurrence: one launch for all 512 steps.
// CTA (nt, ks): phase A computes partial h_t[64 x 256(n0)] over K-slice kb,
// with its Whh slice resident in smem for the entire run. Grid barrier.
// Phase B: fixed-order reduction over 16 splits + leaky-tanh update.
// ---------------------------------------------------------------------------
__global__ __launch_bounds__(256, 1) void recur_kernel(const float* __restrict__ Whh,
                                                       const float* __restrict__ tau,
                                                       const float* __restrict__ h0) {
    extern __shared__ float smem[];
    float* sW = smem;                    // [128][256]  (131072 B)
    float* sH = smem + 128 * 256;        // [64][132]   (33792 B, padded rows)

    const int tid = threadIdx.x;
    const int cid = blockIdx.x;
    const int nt = cid & 7;
    const int ks = cid >> 3;
    const int n0 = nt * 256;
    const int kb = ks * 128;
    const int tcol = tid & 31;           // 32 n-groups of 8
    const int trow = tid >> 5;           // 8 b-groups of 8 (warp-uniform)

    unsigned gen = 0;
    if (tid == 0) gen = *((volatile unsigned*)&g_bar_release);

    // Preload Whh slice [kb..kb+128) x [n0..n0+256) into smem (once, reused 512x)
    for (int i = tid; i < 128 * 64; i += 256) {   // 8192 float4
        int k = i >> 6, n4 = i & 63;
        ((float4*)(sW + k * 256))[n4] =
            ((const float4*)(Whh + (size_t)(kb + k) * NH + n0))[n4];
    }

    // Init g_H[0] slice: elems [cid*1024, cid*1024+1024)
    {
        int base = cid * 1024 + tid * 4;
        int j = base & (NH - 1);
        float4 v = *(const float4*)(h0 + j);
        v.x = fminf(1.f, fmaxf(-1.f, v.x));
        v.y = fminf(1.f, fmaxf(-1.f, v.y));
        v.z = fminf(1.f, fmaxf(-1.f, v.z));
        v.w = fminf(1.f, fmaxf(-1.f, v.w));
        *(float4*)(g_H + base) = v;
    }
    grid_bar(gen);

    float* __restrict__ Pp = g_P + (size_t)ks * BB * NH;
    const int fbase = cid * 1024 + tid * 4;          // phase-B element base
    const int fb = fbase >> 11;
    const int fj = fbase & (NH - 1);
    const float4 tv = *(const float4*)(tau + fj);
    float4 av4;
    av4.x = 1.0f / tv.x; av4.y = 1.0f / tv.y; av4.z = 1.0f / tv.z; av4.w = 1.0f / tv.w;

    for (int t = 0; t < TT; t++) {
        // ---- Phase A: partial GEMM ----
        const float* __restrict__ Ht = g_H + (size_t)t * BB * NH;
        for (int i = tid; i < 64 * 32; i += 256) {   // 2048 float4: sH[b][k]
            int b = i >> 5, k4 = i & 31;
            *(float4*)(sH + b * 132 + k4 * 4) =
                *(const float4*)(Ht + (size_t)b * NH + kb + k4 * 4);
        }
        __syncthreads();

        float acc[8][8];
#pragma unroll
        for (int i = 0; i < 8; i++)
#pragma unroll
            for (int j = 0; j < 8; j++) acc[i][j] = 0.f;

        for (int kk = 0; kk < 128; kk++) {
            float4 w0 = *(const float4*)(sW + kk * 256 + tcol * 8);
            float4 w1 = *(const float4*)(sW + kk * 256 + tcol * 8 + 4);
            float wv[8] = {w0.x, w0.y, w0.z, w0.w, w1.x, w1.y, w1.z, w1.w};
            float hv[8];
#pragma unroll
            for (int i = 0; i < 8; i++) hv[i] = sH[(trow * 8 + i) * 132 + kk];
#pragma unroll
            for (int i = 0; i < 8; i++)
#pragma unroll
                for (int j = 0; j < 8; j++) acc[i][j] += hv[i] * wv[j];
        }

#pragma unroll
        for (int i = 0; i < 8; i++) {
            int b = trow * 8 + i;
            float4* dst = (float4*)(Pp + (size_t)b * NH + n0 + tcol * 8);
            dst[0] = make_float4(acc[i][0], acc[i][1], acc[i][2], acc[i][3]);
            dst[1] = make_float4(acc[i][4], acc[i][5], acc[i][6], acc[i][7]);
        }
        grid_bar(gen);

        // ---- Phase B: reduce splits (fixed order -> deterministic) + update ----
        float4 pre = *(const float4*)(g_X + ((size_t)fb * TT + t) * NH + fj);
#pragma unroll
        for (int s = 0; s < 16; s++) {
            float4 p = __ldcg((const float4*)(g_P + (size_t)s * BB * NH + fbase));
            pre.x += p.x; pre.y += p.y; pre.z += p.z; pre.w += p.w;
        }
        float4 h = *(const float4*)(g_H + (size_t)t * BB * NH + fbase);
        float4 hn;
        hn.x = (1.0f - av4.x) * h.x + av4.x * tanhf(pre.x);
        hn.y = (1.0f - av4.y) * h.y + av4.y * tanhf(pre.y);
        hn.z = (1.0f - av4.z) * h.z + av4.z * tanhf(pre.z);
        hn.w = (1.0f - av4.w) * h.w + av4.w * tanhf(pre.w);
        *(float4*)(g_H + (size_t)(t + 1) * BB * NH + fbase) = hn;
        grid_bar(gen);
    }
}

// ---------------------------------------------------------------------------
// GEMM3: logits = H[t+1] @ W_hy + b_y  (M=32768, K=2048, N=256)
// ---------------------------------------------------------------------------
__global__ __launch_bounds__(256) void gemm3_kernel(const float* __restrict__ Why,
                                                    const float* __restrict__ by,
                                                    float* __restrict__ out) {
    __shared__ float sA[16][129];
    __shared__ float sB[16][128];
    const int m0 = blockIdx.x * 128;
    const int n0 = blockIdx.y * 128;
    const int tid = threadIdx.x;
    const int tcol = tid & 15;
    const int trow = tid >> 4;
    float acc[8][8];
#pragma unroll
    for (int i = 0; i < 8; i++)
#pragma unroll
        for (int j = 0; j < 8; j++) acc[i][j] = 0.f;

    for (int k0 = 0; k0 < NH; k0 += 16) {
#pragma unroll
        for (int i = 0; i < 8; i++) {
            int idx = tid + i * 256;
            int m = idx >> 4, k = idx & 15;
            int gm = m0 + m;
            int b = gm >> 9;
            int tt = gm & (TT - 1);
            sA[k][m] = g_H[((size_t)(tt + 1) * BB + b) * NH + k0 + k];
        }
#pragma unroll
        for (int i = 0; i < 8; i++) {
            int idx = tid + i * 256;
            int k = idx >> 7, n = idx & 127;
            sB[k][n] = Why[(size_t)(k0 + k) * NOUT + n0 + n];
        }
        __syncthreads();
#pragma unroll
        for (int kk = 0; kk < 16; kk++) {
            float av[8], bv[8];
#pragma unroll
            for (int i = 0; i < 8; i++) av[i] = sA[kk][trow * 8 + i];
#pragma unroll
            for (int j = 0; j < 8; j++) bv[j] = sB[kk][tcol * 8 + j];
#pragma unroll
            for (int i = 0; i < 8; i++)
#pragma unroll
                for (int j = 0; j < 8; j++) acc[i][j] += av[i] * bv[j];
        }
        __syncthreads();
    }
#pragma unroll
    for (int i = 0; i < 8; i++) {
        int m = m0 + trow * 8 + i;
#pragma unroll
        for (int j = 0; j < 8; j++) {
            int n = n0 + tcol * 8 + j;
            out[(size_t)m * NOUT + n] = acc[i][j] + by[n];
        }
    }
}

// ---------------------------------------------------------------------------
// Softmax in-place over rows of 256. One warp per row.
// ---------------------------------------------------------------------------
__global__ void softmax_kernel(float* __restrict__ out) {
    int gwarp = (blockIdx.x * blockDim.x + threadIdx.x) >> 5;
    int lane = threadIdx.x & 31;
    float* row = out + (size_t)gwarp * NOUT;
    float v[8];
    float mx = -1e30f;
#pragma unroll
    for (int i = 0; i < 8; i++) {
        v[i] = row[i * 32 + lane];
        mx = fmaxf(mx, v[i]);
    }
#pragma unroll
    for (int o = 16; o; o >>= 1) mx = fmaxf(mx, __shfl_xor_sync(0xffffffffu, mx, o));
    float s = 0.f;
#pragma unroll
    for (int i = 0; i < 8; i++) {
        v[i] = expf(v[i] - mx);
        s += v[i];
    }
#pragma unroll
    for (int o = 16; o; o >>= 1) s += __shfl_xor_sync(0xffffffffu, s, o);
    float inv = 1.0f / s;
#pragma unroll
    for (int i = 0; i < 8; i++) row[i * 32 + lane] = v[i] * inv;
}

extern "C" void kernel_launch(void* const* d_in, const int* in_sizes, int n_in,
                              void* d_out, int out_size) {
    const float* u   = (const float*)d_in[0];
    const float* Wuh = (const float*)d_in[1];
    const float* Whh = (const float*)d_in[2];
    const float* Why = (const float*)d_in[3];
    const float* bh  = (const float*)d_in[4];
    const float* by  = (const float*)d_in[5];
    const float* h0  = (const float*)d_in[6];
    const float* tau = (const float*)d_in[7];
    float* out = (float*)d_out;

    const int smem_bytes = (128 * 256 + 64 * 132) * sizeof(float);  // 164864
    cudaFuncSetAttribute(recur_kernel, cudaFuncAttributeMaxDynamicSharedMemorySize,
                         smem_bytes);

    gemm1_kernel<<<dim3(256, 16), 256>>>(u, Wuh, bh);
    recur_kernel<<<NCTA, 256, smem_bytes>>>(Whh, tau, h0);
    gemm3_kernel<<<dim3(256, 2), 256>>>(Why, by, out);
    softmax_kernel<<<(BB * TT) / 8, 256>>>(out);
}

// round 9
// speedup vs baseline: 1.0807x; 1.0807x over previous
#include <cuda_runtime.h>
#include <math.h>

#define BB   64
#define TT   512
#define NIN  256
#define NH   2048
#define NOUT 256
#define NCTA 128   // 8 n-tiles x 16 k-splits, all co-resident

typedef unsigned long long ull;

// Scratch (device globals; no allocation anywhere)
__device__ float g_X[(size_t)BB * TT * NH];        // [b*T+t][NH]
__device__ float g_H[(size_t)(TT + 1) * BB * NH];  // [t][b][NH]
__device__ float g_P[(size_t)16 * BB * NH];        // [ks][b][NH]
__device__ unsigned g_bar_arrive = 0;
__device__ unsigned g_bar_release = 0;

// Packed fp32x2 helpers (sm_103a FFMA2 — only reachable via PTX)
__device__ __forceinline__ ull bcast2(float x) {
    ull r;
    asm("mov.b64 %0, {%1, %1};" : "=l"(r) : "f"(x));
    return r;
}
__device__ __forceinline__ void ffma2(ull& d, ull a, ull b) {
    asm("fma.rn.f32x2 %0, %1, %2, %0;" : "+l"(d) : "l"(a), "l"(b));
}

// ---------------------------------------------------------------------------
// GEMM1: g_X = u @ W_uh + b_h     (M=32768, K=256, N=2048), 128x128 tile
// ---------------------------------------------------------------------------
__global__ __launch_bounds__(256) void gemm1_kernel(const float* __restrict__ u,
                                                    const float* __restrict__ W,
                                                    const float* __restrict__ bias) {
    __shared__ float sA[16][129];
    __shared__ float sB[16][128];
    const int m0 = blockIdx.x * 128;
    const int n0 = blockIdx.y * 128;
    const int tid = threadIdx.x;
    const int tcol = tid & 15;
    const int trow = tid >> 4;
    ull acc2[8][4];
#pragma unroll
    for (int i = 0; i < 8; i++)
#pragma unroll
        for (int j = 0; j < 4; j++) acc2[i][j] = 0ull;

    for (int k0 = 0; k0 < NIN; k0 += 16) {
#pragma unroll
        for (int i = 0; i < 8; i++) {
            int idx = tid + i * 256;
            int m = idx >> 4, k = idx & 15;
            sA[k][m] = u[(size_t)(m0 + m) * NIN + k0 + k];
        }
#pragma unroll
        for (int i = 0; i < 8; i++) {
            int idx = tid + i * 256;
            int k = idx >> 7, n = idx & 127;
            sB[k][n] = W[(size_t)(k0 + k) * NH + n0 + n];
        }
        __syncthreads();
#pragma unroll
        for (int kk = 0; kk < 16; kk++) {
            const ulonglong2* bp = (const ulonglong2*)(&sB[kk][tcol * 8]);
            ulonglong2 B0 = bp[0], B1 = bp[1];
            ull bv2[4] = {B0.x, B0.y, B1.x, B1.y};
#pragma unroll
            for (int i = 0; i < 8; i++) {
                ull a2 = bcast2(sA[kk][trow * 8 + i]);
#pragma unroll
                for (int j = 0; j < 4; j++) ffma2(acc2[i][j], a2, bv2[j]);
            }
        }
        __syncthreads();
    }
#pragma unroll
    for (int i = 0; i < 8; i++) {
        int m = m0 + trow * 8 + i;
#pragma unroll
        for (int j = 0; j < 4; j++) {
            int n = n0 + tcol * 8 + 2 * j;
            float2 v = *(float2*)&acc2[i][j];
            g_X[(size_t)m * NH + n] = v.x + bias[n];
            g_X[(size_t)m * NH + n + 1] = v.y + bias[n + 1];
        }
    }
}

// ---------------------------------------------------------------------------
// Grid barrier (monotonic release counter). All CTAs co-resident.
// ---------------------------------------------------------------------------
__device__ __forceinline__ void grid_bar(unsigned& gen) {
    __threadfence();
    __syncthreads();
    if (threadIdx.x == 0) {
        unsigned prev = atomicAdd(&g_bar_arrive, 1);
        if (prev == NCTA - 1) {
            g_bar_arrive = 0;
            __threadfence();
            atomicAdd(&g_bar_release, 1);
        } else {
            while (*((volatile unsigned*)&g_bar_release) == gen) { }
        }
        gen++;
    }
    __syncthreads();
}

// ---------------------------------------------------------------------------
// Persistent recurrence: one launch, 512 steps. CTA (nt,ks) keeps its Whh
// slice [128 x 256] in smem for the whole run. Phase A partial GEMM ->
// barrier -> Phase B fixed-order reduce + leaky tanh -> barrier.
// ---------------------------------------------------------------------------
__global__ __launch_bounds__(256, 1) void recur_kernel(const float* __restrict__ Whh,
                                                       const float* __restrict__ tau,
                                                       const float* __restrict__ h0) {
    extern __shared__ float smem[];
    float* sW = smem;                    // [128][256]
    float* sH = smem + 128 * 256;        // [64][132]

    const int tid = threadIdx.x;
    const int cid = blockIdx.x;
    const int nt = cid & 7;
    const int ks = cid >> 3;
    const int n0 = nt * 256;
    const int kb = ks * 128;
    const int tcol = tid & 31;           // 32 n-groups of 8
    const int trow = tid >> 5;           // 8 b-groups of 8 (warp-uniform)

    unsigned gen = 0;
    if (tid == 0) gen = *((volatile unsigned*)&g_bar_release);

    // Preload Whh slice (reused 512x)
    for (int i = tid; i < 128 * 64; i += 256) {
        int k = i >> 6, n4 = i & 63;
        ((float4*)(sW + k * 256))[n4] =
            ((const float4*)(Whh + (size_t)(kb + k) * NH + n0))[n4];
    }

    // Init g_H[0]
    {
        int base = cid * 1024 + tid * 4;
        int j = base & (NH - 1);
        float4 v = *(const float4*)(h0 + j);
        v.x = fminf(1.f, fmaxf(-1.f, v.x));
        v.y = fminf(1.f, fmaxf(-1.f, v.y));
        v.z = fminf(1.f, fmaxf(-1.f, v.z));
        v.w = fminf(1.f, fmaxf(-1.f, v.w));
        *(float4*)(g_H + base) = v;
    }
    grid_bar(gen);

    float* __restrict__ Pp = g_P + (size_t)ks * BB * NH;
    const int fbase = cid * 1024 + tid * 4;
    const int fb = fbase >> 11;
    const int fj = fbase & (NH - 1);
    const float4 tv = *(const float4*)(tau + fj);
    float4 av4;
    av4.x = 1.0f / tv.x; av4.y = 1.0f / tv.y; av4.z = 1.0f / tv.z; av4.w = 1.0f / tv.w;

    for (int t = 0; t < TT; t++) {
        // ---- Phase A: partial GEMM (packed f32x2) ----
        const float* __restrict__ Ht = g_H + (size_t)t * BB * NH;
        for (int i = tid; i < 64 * 32; i += 256) {
            int b = i >> 5, k4 = i & 31;
            *(float4*)(sH + b * 132 + k4 * 4) =
                *(const float4*)(Ht + (size_t)b * NH + kb + k4 * 4);
        }
        __syncthreads();

        ull acc2[8][4];
#pragma unroll
        for (int i = 0; i < 8; i++)
#pragma unroll
            for (int j = 0; j < 4; j++) acc2[i][j] = 0ull;

#pragma unroll 2
        for (int kk = 0; kk < 128; kk++) {
            const ulonglong2* wp = (const ulonglong2*)(sW + kk * 256 + tcol * 8);
            ulonglong2 W0 = wp[0], W1 = wp[1];
            ull wv2[4] = {W0.x, W0.y, W1.x, W1.y};
#pragma unroll
            for (int i = 0; i < 8; i++) {
                ull h2 = bcast2(sH[(trow * 8 + i) * 132 + kk]);
#pragma unroll
                for (int j = 0; j < 4; j++) ffma2(acc2[i][j], h2, wv2[j]);
            }
        }

#pragma unroll
        for (int i = 0; i < 8; i++) {
            int b = trow * 8 + i;
            ulonglong2* dst = (ulonglong2*)(Pp + (size_t)b * NH + n0 + tcol * 8);
            dst[0] = make_ulonglong2(acc2[i][0], acc2[i][1]);
            dst[1] = make_ulonglong2(acc2[i][2], acc2[i][3]);
        }
        grid_bar(gen);

        // ---- Phase B: fixed-order reduce + leaky tanh ----
        float4 pre = *(const float4*)(g_X + ((size_t)fb * TT + t) * NH + fj);
#pragma unroll
        for (int s = 0; s < 16; s++) {
            float4 p = __ldcg((const float4*)(g_P + (size_t)s * BB * NH + fbase));
            pre.x += p.x; pre.y += p.y; pre.z += p.z; pre.w += p.w;
        }
        float4 h = *(const float4*)(g_H + (size_t)t * BB * NH + fbase);
        float4 hn;
        hn.x = (1.0f - av4.x) * h.x + av4.x * tanhf(pre.x);
        hn.y = (1.0f - av4.y) * h.y + av4.y * tanhf(pre.y);
        hn.z = (1.0f - av4.z) * h.z + av4.z * tanhf(pre.z);
        hn.w = (1.0f - av4.w) * h.w + av4.w * tanhf(pre.w);
        *(float4*)(g_H + (size_t)(t + 1) * BB * NH + fbase) = hn;
        grid_bar(gen);
    }
}

// ---------------------------------------------------------------------------
// GEMM3: logits = H[t+1] @ W_hy + b_y  (M=32768, K=2048, N=256)
// ---------------------------------------------------------------------------
__global__ __launch_bounds__(256) void gemm3_kernel(const float* __restrict__ Why,
                                                    const float* __restrict__ by,
                                                    float* __restrict__ out) {
    __shared__ float sA[16][129];
    __shared__ float sB[16][128];
    const int m0 = blockIdx.x * 128;
    const int n0 = blockIdx.y * 128;
    const int tid = threadIdx.x;
    const int tcol = tid & 15;
    const int trow = tid >> 4;
    ull acc2[8][4];
#pragma unroll
    for (int i = 0; i < 8; i++)
#pragma unroll
        for (int j = 0; j < 4; j++) acc2[i][j] = 0ull;

    for (int k0 = 0; k0 < NH; k0 += 16) {
#pragma unroll
        for (int i = 0; i < 8; i++) {
            int idx = tid + i * 256;
            int m = idx >> 4, k = idx & 15;
            int gm = m0 + m;
            int b = gm >> 9;
            int tt = gm & (TT - 1);
            sA[k][m] = g_H[((size_t)(tt + 1) * BB + b) * NH + k0 + k];
        }
#pragma unroll
        for (int i = 0; i < 8; i++) {
            int idx = tid + i * 256;
            int k = idx >> 7, n = idx & 127;
            sB[k][n] = Why[(size_t)(k0 + k) * NOUT + n0 + n];
        }
        __syncthreads();
#pragma unroll
        for (int kk = 0; kk < 16; kk++) {
            const ulonglong2* bp = (const ulonglong2*)(&sB[kk][tcol * 8]);
            ulonglong2 B0 = bp[0], B1 = bp[1];
            ull bv2[4] = {B0.x, B0.y, B1.x, B1.y};
#pragma unroll
            for (int i = 0; i < 8; i++) {
                ull a2 = bcast2(sA[kk][trow * 8 + i]);
#pragma unroll
                for (int j = 0; j < 4; j++) ffma2(acc2[i][j], a2, bv2[j]);
            }
        }
        __syncthreads();
    }
#pragma unroll
    for (int i = 0; i < 8; i++) {
        int m = m0 + trow * 8 + i;
#pragma unroll
        for (int j = 0; j < 4; j++) {
            int n = n0 + tcol * 8 + 2 * j;
            float2 v = *(float2*)&acc2[i][j];
            out[(size_t)m * NOUT + n] = v.x + by[n];
            out[(size_t)m * NOUT + n + 1] = v.y + by[n + 1];
        }
    }
}

// ---------------------------------------------------------------------------
// Softmax in-place over rows of 256. One warp per row.
// ---------------------------------------------------------------------------
__global__ void softmax_kernel(float* __restrict__ out) {
    int gwarp = (blockIdx.x * blockDim.x + threadIdx.x) >> 5;
    int lane = threadIdx.x & 31;
    float* row = out + (size_t)gwarp * NOUT;
    float v[8];
    float mx = -1e30f;
#pragma unroll
    for (int i = 0; i < 8; i++) {
        v[i] = row[i * 32 + lane];
        mx = fmaxf(mx, v[i]);
    }
#pragma unroll
    for (int o = 16; o; o >>= 1) mx = fmaxf(mx, __shfl_xor_sync(0xffffffffu, mx, o));
    float s = 0.f;
#pragma unroll
    for (int i = 0; i < 8; i++) {
        v[i] = expf(v[i] - mx);
        s += v[i];
    }
#pragma unroll
    for (int o = 16; o; o >>= 1) s += __shfl_xor_sync(0xffffffffu, s, o);
    float inv = 1.0f / s;
#pragma unroll
    for (int i = 0; i < 8; i++) row[i * 32 + lane] = v[i] * inv;
}

extern "C" void kernel_launch(void* const* d_in, const int* in_sizes, int n_in,
                              void* d_out, int out_size) {
    const float* u   = (const float*)d_in[0];
    const float* Wuh = (const float*)d_in[1];
    const float* Whh = (const float*)d_in[2];
    const float* Why = (const float*)d_in[3];
    const float* bh  = (const float*)d_in[4];
    const float* by  = (const float*)d_in[5];
    const float* h0  = (const float*)d_in[6];
    const float* tau = (const float*)d_in[7];
    float* out = (float*)d_out;

    const int smem_bytes = (128 * 256 + 64 * 132) * sizeof(float);  // 164864
    cudaFuncSetAttribute(recur_kernel, cudaFuncAttributeMaxDynamicSharedMemorySize,
                         smem_bytes);

    gemm1_kernel<<<dim3(256, 16), 256>>>(u, Wuh, bh);
    recur_kernel<<<NCTA, 256, smem_bytes>>>(Whh, tau, h0);
    gemm3_kernel<<<dim3(256, 2), 256>>>(Why, by, out);
    softmax_kernel<<<(BB * TT) / 8, 256>>>(out);
}